// round 2
// baseline (speedup 1.0000x reference)
#include <cuda_runtime.h>

// ============================================================================
// AdaptiveTimeFrequency via FFT circular correlation.
//   y[b,f,:] = ifft( FFT(x_b) * conj(FFT(r_f)) ),  r_f = softmax(wp_f)*cos(2pi freq_f n)
// Packing: FFT(x[2b] + i*x[2b+1]) -> one ifft gives two real rows.
// R2: fused fwd-FFT kernel; k_main with filter-pair tiling + Hermitian-R
//     smem staging + streaming stores. L2 traffic 384MB -> 256MB.
// ============================================================================

#define L_FFT 4096
#define NTHREADS 256
#define F_FILT 32
#define B_BATCH 256
#define BP (B_BATCH / 2)
#define HALF (L_FFT / 2)  // 2048

__device__ float2 g_Zf[BP * L_FFT];      // packed spectra of x row pairs (4 MB)
__device__ float2 g_Rf[F_FILT * L_FFT];  // FFT(r_f) / L   (1 MB)

// ---------------- complex helpers ----------------
__device__ __forceinline__ float2 cadd(float2 a, float2 b) { return make_float2(a.x + b.x, a.y + b.y); }
__device__ __forceinline__ float2 csub(float2 a, float2 b) { return make_float2(a.x - b.x, a.y - b.y); }
__device__ __forceinline__ float2 cmul(float2 a, float2 b) {
    return make_float2(fmaf(a.x, b.x, -a.y * b.y), fmaf(a.x, b.y, a.y * b.x));
}
// a * conj(b)
__device__ __forceinline__ float2 cmulc(float2 a, float2 b) {
    return make_float2(fmaf(a.x, b.x, a.y * b.y), fmaf(a.y, b.x, -a.x * b.y));
}

// 16th roots of unity
__device__ __constant__ float C16T[16] = {
    1.0f,  0.92387953251128675613f,  0.70710678118654752440f,  0.38268343236508977173f,
    0.0f, -0.38268343236508977173f, -0.70710678118654752440f, -0.92387953251128675613f,
   -1.0f, -0.92387953251128675613f, -0.70710678118654752440f, -0.38268343236508977173f,
    0.0f,  0.38268343236508977173f,  0.70710678118654752440f,  0.92387953251128675613f};
__device__ __constant__ float S16T[16] = {
    0.0f,  0.38268343236508977173f,  0.70710678118654752440f,  0.92387953251128675613f,
    1.0f,  0.92387953251128675613f,  0.70710678118654752440f,  0.38268343236508977173f,
    0.0f, -0.38268343236508977173f, -0.70710678118654752440f, -0.92387953251128675613f,
   -1.0f, -0.92387953251128675613f, -0.70710678118654752440f, -0.38268343236508977173f};

template <int DIR>
__device__ __forceinline__ float2 cmulw16(float2 a, int m) {
    float2 w = make_float2(C16T[m & 15], (float)DIR * S16T[m & 15]);
    return cmul(a, w);
}

template <int DIR>
__device__ __forceinline__ void fft16(float2 v[16]) {
    float2 u[16];
#pragma unroll
    for (int q = 0; q < 4; ++q) {
        float2 a = v[q], b = v[q + 4], c = v[q + 8], d = v[q + 12];
        float2 t0 = cadd(a, c), t1 = csub(a, c), t2 = cadd(b, d), t3 = csub(b, d);
        float2 jt3 = make_float2((float)(-DIR) * t3.y, (float)DIR * t3.x);
        u[4 * q + 0] = cadd(t0, t2);
        u[4 * q + 1] = cadd(t1, jt3);
        u[4 * q + 2] = csub(t0, t2);
        u[4 * q + 3] = csub(t1, jt3);
    }
#pragma unroll
    for (int q = 0; q < 4; ++q) {
        float2 a = u[q];
        float2 b = (q == 0) ? u[q + 4]  : cmulw16<DIR>(u[q + 4], q);
        float2 c = (q == 0) ? u[q + 8]  : cmulw16<DIR>(u[q + 8], 2 * q);
        float2 d = (q == 0) ? u[q + 12] : cmulw16<DIR>(u[q + 12], 3 * q);
        float2 t0 = cadd(a, c), t1 = csub(a, c), t2 = cadd(b, d), t3 = csub(b, d);
        float2 jt3 = make_float2((float)(-DIR) * t3.y, (float)DIR * t3.x);
        v[q]      = cadd(t0, t2);
        v[q + 4]  = cadd(t1, jt3);
        v[q + 8]  = csub(t0, t2);
        v[q + 12] = csub(t1, jt3);
    }
}

__device__ __forceinline__ int pad(int i) { return i + (i >> 4); }
#define SMEM_ELEMS (L_FFT + (L_FFT >> 4))  // 4352

__device__ __forceinline__ void twiddle_chain(float2 v[16], float ang) {
    float sn, cs;
    sincosf(ang, &sn, &cs);
    float2 w1 = make_float2(cs, sn);
    float2 w = w1;
    v[1] = cmul(v[1], w);
#pragma unroll
    for (int r = 2; r < 16; ++r) {
        w = cmul(w, w1);
        v[r] = cmul(v[r], w);
    }
}

// Full 4096-pt FFT, 256 threads. Input: v[r] = in[j + 256*r]. Output: v[k] = out[j+256*k].
// NOTE: no trailing sync; caller must __syncthreads() before reusing s.
template <int DIR>
__device__ __forceinline__ void fft4096(float2 v[16], float2* s, int j) {
    const float TWO_PI = 6.28318530717958647692f;
    fft16<DIR>(v);
#pragma unroll
    for (int k = 0; k < 16; ++k) s[pad(16 * j + k)] = v[k];
    __syncthreads();
    {
#pragma unroll
        for (int r = 0; r < 16; ++r) v[r] = s[pad(j + 256 * r)];
        float ang = (float)DIR * (TWO_PI / 256.0f) * (float)(j & 15);
        twiddle_chain(v, ang);
        fft16<DIR>(v);
        int idxD = (j >> 4) * 256 + (j & 15);
        __syncthreads();
#pragma unroll
        for (int k = 0; k < 16; ++k) s[pad(idxD + 16 * k)] = v[k];
    }
    __syncthreads();
    {
#pragma unroll
        for (int r = 0; r < 16; ++r) v[r] = s[pad(j + 256 * r)];
        float ang = (float)DIR * (TWO_PI / 4096.0f) * (float)j;
        twiddle_chain(v, ang);
        fft16<DIR>(v);
    }
}

// ---------------- Kernel 1: fused forward FFTs ----------------
// blocks [0, BP)        : packed x-pair FFT -> g_Zf
// blocks [BP, BP+F_FILT): softmax atom FFT  -> g_Rf
__global__ __launch_bounds__(NTHREADS) void k_fft_rx(const float* __restrict__ x,
                                                     const float* __restrict__ wp,
                                                     const float* __restrict__ fp) {
    __shared__ float2 s[SMEM_ELEMS];
    __shared__ float red[8];
    int j = threadIdx.x;

    if (blockIdx.x < BP) {
        int bp = blockIdx.x;
        const float* x1 = x + (size_t)(2 * bp) * L_FFT;
        const float* x2 = x + (size_t)(2 * bp + 1) * L_FFT;
        float2 v[16];
#pragma unroll
        for (int r = 0; r < 16; ++r) {
            int i = j + 256 * r;
            v[r] = make_float2(x1[i], x2[i]);
        }
        fft4096<-1>(v, s, j);
#pragma unroll
        for (int k = 0; k < 16; ++k) g_Zf[(size_t)bp * L_FFT + j + 256 * k] = v[k];
    } else {
        int f = blockIdx.x - BP;
        const float* row = wp + (size_t)f * L_FFT;

        float w[16];
        float mx = -3.4e38f;
#pragma unroll
        for (int r = 0; r < 16; ++r) {
            w[r] = row[j + 256 * r];
            mx = fmaxf(mx, w[r]);
        }
#pragma unroll
        for (int off = 16; off; off >>= 1) mx = fmaxf(mx, __shfl_xor_sync(0xffffffffu, mx, off));
        if ((j & 31) == 0) red[j >> 5] = mx;
        __syncthreads();
        float bm = red[0];
#pragma unroll
        for (int i = 1; i < 8; ++i) bm = fmaxf(bm, red[i]);
        __syncthreads();

        float se = 0.0f;
#pragma unroll
        for (int r = 0; r < 16; ++r) {
            w[r] = expf(w[r] - bm);
            se += w[r];
        }
#pragma unroll
        for (int off = 16; off; off >>= 1) se += __shfl_xor_sync(0xffffffffu, se, off);
        if ((j & 31) == 0) red[j >> 5] = se;
        __syncthreads();
        float bs = 0.0f;
#pragma unroll
        for (int i = 0; i < 8; ++i) bs += red[i];
        __syncthreads();

        float scale = 1.0f / (bs * (float)L_FFT);  // softmax norm + ifft 1/L
        float freq = 0.5f / (1.0f + expf(-fp[f]));
        float a = -6.2831853071795864769f * freq;

        float2 v[16];
#pragma unroll
        for (int r = 0; r < 16; ++r) {
            int n = j + 256 * r;
            float ph = a * (float)n;
            v[r] = make_float2(w[r] * scale * cosf(ph), 0.0f);
        }
        fft4096<-1>(v, s, j);
#pragma unroll
        for (int k = 0; k < 16; ++k) g_Rf[(size_t)f * L_FFT + j + 256 * k] = v[k];
    }
}

// ---------------- Kernel 2: product + inverse FFT + write ----------------
// Grid (F/2, BP): each CTA handles one bp and TWO filters (2f, 2f+1).
// R is Hermitian (real atoms): stage only R[0..2048] in smem, mirror the rest.
// smem: ws[4352] | stash[4096] | r0h[2049] | r1h[2049]  = 100,368 B -> 2 CTAs/SM
#define WS_OFF 0
#define STASH_OFF SMEM_ELEMS            // 4352
#define R0_OFF (STASH_OFF + L_FFT)      // 8448
#define R1_OFF (R0_OFF + HALF + 1)      // 10497
#define MAIN_SMEM_F2 (R1_OFF + HALF + 1)  // 12546 float2
#define MAIN_SMEM_BYTES (MAIN_SMEM_F2 * 8)  // 100368

__global__ __launch_bounds__(NTHREADS) void k_main2(float* __restrict__ out) {
    extern __shared__ float2 sm[];
    float2* ws    = sm + WS_OFF;
    float2* stash = sm + STASH_OFF;
    float2* r0h   = sm + R0_OFF;
    float2* r1h   = sm + R1_OFF;

    int fpair = blockIdx.x;
    int f0 = 2 * fpair, f1 = 2 * fpair + 1;
    int bp = blockIdx.y;
    int j = threadIdx.x;

    const float2* __restrict__ Z  = g_Zf + (size_t)bp * L_FFT;
    const float2* __restrict__ R0 = g_Rf + (size_t)f0 * L_FFT;
    const float2* __restrict__ R1 = g_Rf + (size_t)f1 * L_FFT;

    // stage first halves of R0, R1 (Hermitian symmetry covers the rest)
    for (int t = j; t <= HALF; t += NTHREADS) {
        r0h[t] = R0[t];
        r1h[t] = R1[t];
    }
    __syncthreads();

    // products: P = Z * conj(R). For i>HALF: R[i]=conj(R[L-i]) => P = Z*R[L-i].
    float2 v[16];
#pragma unroll
    for (int r = 0; r < 16; ++r) {
        int i = j + 256 * r;
        float2 z = Z[i];
        float2 p0, p1;
        if (i <= HALF) {
            p0 = cmulc(z, r0h[i]);
            p1 = cmulc(z, r1h[i]);
        } else {
            p0 = cmul(z, r0h[L_FFT - i]);
            p1 = cmul(z, r1h[L_FFT - i]);
        }
        v[r] = p0;
        stash[i] = p1;  // same-thread write/read later; no extra sync needed
    }

    fft4096<1>(v, ws, j);  // unscaled inverse (1/L folded into R)

    {
        float* o1 = out + ((size_t)(2 * bp) * F_FILT + f0) * L_FFT;
        float* o2 = out + ((size_t)(2 * bp + 1) * F_FILT + f0) * L_FFT;
#pragma unroll
        for (int k = 0; k < 16; ++k) {
            int i = j + 256 * k;
            __stcs(o1 + i, v[k].x);
            __stcs(o2 + i, v[k].y);
        }
    }
    __syncthreads();  // ws reuse hazard between the two iffts

#pragma unroll
    for (int r = 0; r < 16; ++r) v[r] = stash[j + 256 * r];

    fft4096<1>(v, ws, j);

    {
        float* o1 = out + ((size_t)(2 * bp) * F_FILT + f1) * L_FFT;
        float* o2 = out + ((size_t)(2 * bp + 1) * F_FILT + f1) * L_FFT;
#pragma unroll
        for (int k = 0; k < 16; ++k) {
            int i = j + 256 * k;
            __stcs(o1 + i, v[k].x);
            __stcs(o2 + i, v[k].y);
        }
    }
}

extern "C" void kernel_launch(void* const* d_in, const int* in_sizes, int n_in,
                              void* d_out, int out_size) {
    (void)in_sizes; (void)n_in; (void)out_size;
    const float* x  = (const float*)d_in[0];
    const float* wp = (const float*)d_in[1];
    const float* fp = (const float*)d_in[2];
    float* out = (float*)d_out;

    cudaFuncSetAttribute(k_main2, cudaFuncAttributeMaxDynamicSharedMemorySize, MAIN_SMEM_BYTES);

    k_fft_rx<<<BP + F_FILT, NTHREADS>>>(x, wp, fp);
    dim3 grid(F_FILT / 2, BP);
    k_main2<<<grid, NTHREADS, MAIN_SMEM_BYTES>>>(out);
}

// round 4
// speedup vs baseline: 1.3972x; 1.3972x over previous
#include <cuda_runtime.h>

// ============================================================================
// AdaptiveTimeFrequency via FFT circular correlation.
//   y[b,f,:] = ifft( FFT(x_b) * conj(FFT(r_f)) ),  r_f = softmax(wp_f)*cos(2pi freq_f n)
// Packing: FFT(x[2b] + i*x[2b+1]) -> one ifft gives two real rows.
// R3: back to high-occupancy one-filter-per-CTA k_main (R2 occupancy lesson),
//     fused forward FFTs, fast MUFU twiddles (args < 0.4 rad), streaming stores.
// ============================================================================

#define L_FFT 4096
#define NTHREADS 256
#define F_FILT 32
#define B_BATCH 256
#define BP (B_BATCH / 2)

__device__ float2 g_Zf[BP * L_FFT];      // packed spectra of x row pairs (4 MB)
__device__ float2 g_Rf[F_FILT * L_FFT];  // FFT(r_f) / L   (1 MB)

// ---------------- complex helpers ----------------
__device__ __forceinline__ float2 cadd(float2 a, float2 b) { return make_float2(a.x + b.x, a.y + b.y); }
__device__ __forceinline__ float2 csub(float2 a, float2 b) { return make_float2(a.x - b.x, a.y - b.y); }
__device__ __forceinline__ float2 cmul(float2 a, float2 b) {
    return make_float2(fmaf(a.x, b.x, -a.y * b.y), fmaf(a.x, b.y, a.y * b.x));
}
// a * conj(b)
__device__ __forceinline__ float2 cmulc(float2 a, float2 b) {
    return make_float2(fmaf(a.x, b.x, a.y * b.y), fmaf(a.y, b.x, -a.x * b.y));
}

// 16th roots of unity
__device__ __constant__ float C16T[16] = {
    1.0f,  0.92387953251128675613f,  0.70710678118654752440f,  0.38268343236508977173f,
    0.0f, -0.38268343236508977173f, -0.70710678118654752440f, -0.92387953251128675613f,
   -1.0f, -0.92387953251128675613f, -0.70710678118654752440f, -0.38268343236508977173f,
    0.0f,  0.38268343236508977173f,  0.70710678118654752440f,  0.92387953251128675613f};
__device__ __constant__ float S16T[16] = {
    0.0f,  0.38268343236508977173f,  0.70710678118654752440f,  0.92387953251128675613f,
    1.0f,  0.92387953251128675613f,  0.70710678118654752440f,  0.38268343236508977173f,
    0.0f, -0.38268343236508977173f, -0.70710678118654752440f, -0.92387953251128675613f,
   -1.0f, -0.92387953251128675613f, -0.70710678118654752440f, -0.38268343236508977173f};

template <int DIR>
__device__ __forceinline__ float2 cmulw16(float2 a, int m) {
    float2 w = make_float2(C16T[m & 15], (float)DIR * S16T[m & 15]);
    return cmul(a, w);
}

template <int DIR>
__device__ __forceinline__ void fft16(float2 v[16]) {
    float2 u[16];
#pragma unroll
    for (int q = 0; q < 4; ++q) {
        float2 a = v[q], b = v[q + 4], c = v[q + 8], d = v[q + 12];
        float2 t0 = cadd(a, c), t1 = csub(a, c), t2 = cadd(b, d), t3 = csub(b, d);
        float2 jt3 = make_float2((float)(-DIR) * t3.y, (float)DIR * t3.x);
        u[4 * q + 0] = cadd(t0, t2);
        u[4 * q + 1] = cadd(t1, jt3);
        u[4 * q + 2] = csub(t0, t2);
        u[4 * q + 3] = csub(t1, jt3);
    }
#pragma unroll
    for (int q = 0; q < 4; ++q) {
        float2 a = u[q];
        float2 b = (q == 0) ? u[q + 4]  : cmulw16<DIR>(u[q + 4], q);
        float2 c = (q == 0) ? u[q + 8]  : cmulw16<DIR>(u[q + 8], 2 * q);
        float2 d = (q == 0) ? u[q + 12] : cmulw16<DIR>(u[q + 12], 3 * q);
        float2 t0 = cadd(a, c), t1 = csub(a, c), t2 = cadd(b, d), t3 = csub(b, d);
        float2 jt3 = make_float2((float)(-DIR) * t3.y, (float)DIR * t3.x);
        v[q]      = cadd(t0, t2);
        v[q + 4]  = cadd(t1, jt3);
        v[q + 8]  = csub(t0, t2);
        v[q + 12] = csub(t1, jt3);
    }
}

__device__ __forceinline__ int pad(int i) { return i + (i >> 4); }
#define SMEM_ELEMS (L_FFT + (L_FFT >> 4))  // 4352

// twiddle chain: v[r] *= exp(i*r*ang). |ang| < 0.4 rad in both call sites, so
// MUFU-based __sincosf is safe (abs err ~1e-7; chained x15 -> ~1e-6 << 1e-3).
__device__ __forceinline__ void twiddle_chain(float2 v[16], float ang) {
    float sn, cs;
    __sincosf(ang, &sn, &cs);
    float2 w1 = make_float2(cs, sn);
    float2 w = w1;
    v[1] = cmul(v[1], w);
#pragma unroll
    for (int r = 2; r < 16; ++r) {
        w = cmul(w, w1);
        v[r] = cmul(v[r], w);
    }
}

// Full 4096-pt FFT, 256 threads. Input: v[r] = in[j + 256*r]. Output: v[k] = out[j+256*k].
template <int DIR>
__device__ __forceinline__ void fft4096(float2 v[16], float2* s, int j) {
    const float TWO_PI = 6.28318530717958647692f;
    fft16<DIR>(v);
#pragma unroll
    for (int k = 0; k < 16; ++k) s[pad(16 * j + k)] = v[k];
    __syncthreads();
    {
#pragma unroll
        for (int r = 0; r < 16; ++r) v[r] = s[pad(j + 256 * r)];
        float ang = (float)DIR * (TWO_PI / 256.0f) * (float)(j & 15);
        twiddle_chain(v, ang);
        fft16<DIR>(v);
        int idxD = (j >> 4) * 256 + (j & 15);
        __syncthreads();
#pragma unroll
        for (int k = 0; k < 16; ++k) s[pad(idxD + 16 * k)] = v[k];
    }
    __syncthreads();
    {
#pragma unroll
        for (int r = 0; r < 16; ++r) v[r] = s[pad(j + 256 * r)];
        float ang = (float)DIR * (TWO_PI / 4096.0f) * (float)j;
        twiddle_chain(v, ang);
        fft16<DIR>(v);
    }
}

// ---------------- Kernel 1: fused forward FFTs ----------------
// blocks [0, BP)        : packed x-pair FFT -> g_Zf
// blocks [BP, BP+F_FILT): softmax atom FFT  -> g_Rf
__global__ __launch_bounds__(NTHREADS) void k_fft_rx(const float* __restrict__ x,
                                                     const float* __restrict__ wp,
                                                     const float* __restrict__ fp) {
    __shared__ float2 s[SMEM_ELEMS];
    __shared__ float red[8];
    int j = threadIdx.x;

    if (blockIdx.x < BP) {
        int bp = blockIdx.x;
        const float* x1 = x + (size_t)(2 * bp) * L_FFT;
        const float* x2 = x + (size_t)(2 * bp + 1) * L_FFT;
        float2 v[16];
#pragma unroll
        for (int r = 0; r < 16; ++r) {
            int i = j + 256 * r;
            v[r] = make_float2(x1[i], x2[i]);
        }
        fft4096<-1>(v, s, j);
#pragma unroll
        for (int k = 0; k < 16; ++k) g_Zf[(size_t)bp * L_FFT + j + 256 * k] = v[k];
    } else {
        int f = blockIdx.x - BP;
        const float* row = wp + (size_t)f * L_FFT;

        float w[16];
        float mx = -3.4e38f;
#pragma unroll
        for (int r = 0; r < 16; ++r) {
            w[r] = row[j + 256 * r];
            mx = fmaxf(mx, w[r]);
        }
#pragma unroll
        for (int off = 16; off; off >>= 1) mx = fmaxf(mx, __shfl_xor_sync(0xffffffffu, mx, off));
        if ((j & 31) == 0) red[j >> 5] = mx;
        __syncthreads();
        float bm = red[0];
#pragma unroll
        for (int i = 1; i < 8; ++i) bm = fmaxf(bm, red[i]);
        __syncthreads();

        float se = 0.0f;
#pragma unroll
        for (int r = 0; r < 16; ++r) {
            w[r] = expf(w[r] - bm);
            se += w[r];
        }
#pragma unroll
        for (int off = 16; off; off >>= 1) se += __shfl_xor_sync(0xffffffffu, se, off);
        if ((j & 31) == 0) red[j >> 5] = se;
        __syncthreads();
        float bs = 0.0f;
#pragma unroll
        for (int i = 0; i < 8; ++i) bs += red[i];
        __syncthreads();

        float scale = 1.0f / (bs * (float)L_FFT);  // softmax norm + ifft 1/L
        float freq = 0.5f / (1.0f + expf(-fp[f]));
        float a = -6.2831853071795864769f * freq;

        float2 v[16];
#pragma unroll
        for (int r = 0; r < 16; ++r) {
            int n = j + 256 * r;
            float ph = a * (float)n;  // up to ~1.3e4: keep precise cosf here
            v[r] = make_float2(w[r] * scale * cosf(ph), 0.0f);
        }
        fft4096<-1>(v, s, j);
#pragma unroll
        for (int k = 0; k < 16; ++k) g_Rf[(size_t)f * L_FFT + j + 256 * k] = v[k];
    }
}

// ---------------- Kernel 2: product + inverse FFT + write ----------------
// One (f, bp) per CTA; static 34.8 KB smem -> ~5-6 CTAs/SM (occupancy is king).
__global__ __launch_bounds__(NTHREADS) void k_main(float* __restrict__ out) {
    __shared__ float2 s[SMEM_ELEMS];
    int f = blockIdx.x;
    int bp = blockIdx.y;
    int j = threadIdx.x;

    const float2* __restrict__ Z = g_Zf + (size_t)bp * L_FFT;
    const float2* __restrict__ R = g_Rf + (size_t)f * L_FFT;

    float2 v[16];
#pragma unroll
    for (int r = 0; r < 16; ++r) {
        int i = j + 256 * r;
        float2 z = Z[i];
        float2 rr = R[i];
        v[r] = cmulc(z, rr);  // z * conj(r); 1/L folded into R
    }
    fft4096<1>(v, s, j);  // inverse, unscaled

    float* __restrict__ o1 = out + ((size_t)(2 * bp) * F_FILT + f) * L_FFT;
    float* __restrict__ o2 = out + ((size_t)(2 * bp + 1) * F_FILT + f) * L_FFT;
#pragma unroll
    for (int k = 0; k < 16; ++k) {
        int i = j + 256 * k;
        __stcs(o1 + i, v[k].x);  // streaming: don't pollute L2 (Z/R resident)
        __stcs(o2 + i, v[k].y);
    }
}

extern "C" void kernel_launch(void* const* d_in, const int* in_sizes, int n_in,
                              void* d_out, int out_size) {
    (void)in_sizes; (void)n_in; (void)out_size;
    const float* x  = (const float*)d_in[0];
    const float* wp = (const float*)d_in[1];
    const float* fp = (const float*)d_in[2];
    float* out = (float*)d_out;

    k_fft_rx<<<BP + F_FILT, NTHREADS>>>(x, wp, fp);
    dim3 grid(F_FILT, BP);
    k_main<<<grid, NTHREADS>>>(out);
}

// round 7
// speedup vs baseline: 1.5187x; 1.0870x over previous
#include <cuda_runtime.h>

// ============================================================================
// AdaptiveTimeFrequency via FFT circular correlation.
//   y[b,f,:] = ifft( FFT(x_b) * conj(FFT(r_f)) ),  r_f = softmax(wp_f)*cos(2pi freq_f n)
// Packing: FFT(x[2b] + i*x[2b+1]) -> one ifft gives two real rows.
// R5: f32x2 packed butterflies (Blackwell FFMA2 path), cheap r-branch cosine
//     recurrence + __expf, fused forward FFTs, streaming stores.
// ============================================================================

#define L_FFT 4096
#define NTHREADS 256
#define F_FILT 32
#define B_BATCH 256
#define BP (B_BATCH / 2)

typedef unsigned long long u64;

__device__ float2 g_Zf[BP * L_FFT];      // packed spectra of x row pairs (4 MB)
__device__ float2 g_Rf[F_FILT * L_FFT];  // FFT(r_f) / L   (1 MB)

// ---------------- packed f32x2 primitives ----------------
__device__ __forceinline__ u64 pk2(float x, float y) {
    u64 r; asm("mov.b64 %0, {%1, %2};" : "=l"(r) : "f"(x), "f"(y)); return r;
}
__device__ __forceinline__ void upk(u64 a, float& x, float& y) {
    asm("mov.b64 {%0, %1}, %2;" : "=f"(x), "=f"(y) : "l"(a));
}
__device__ __forceinline__ u64 padd(u64 a, u64 b) {
    u64 r; asm("add.rn.f32x2 %0, %1, %2;" : "=l"(r) : "l"(a), "l"(b)); return r;
}
__device__ __forceinline__ u64 pmul(u64 a, u64 b) {
    u64 r; asm("mul.rn.f32x2 %0, %1, %2;" : "=l"(r) : "l"(a), "l"(b)); return r;
}
__device__ __forceinline__ u64 pfma(u64 a, u64 b, u64 c) {
    u64 r; asm("fma.rn.f32x2 %0, %1, %2, %3;" : "=l"(r) : "l"(a), "l"(b), "l"(c)); return r;
}
#define PK_NEG1 0xBF800000BF800000ULL  // (-1,-1)
__device__ __forceinline__ u64 psub(u64 a, u64 b) { return pfma(b, PK_NEG1, a); }  // a-b (exact)
__device__ __forceinline__ u64 pswap(u64 a) {
    float x, y; upk(a, x, y); return pk2(y, x);
}

// CJ<DIR>  = pack(-DIR, +DIR): out = t1 + DIR*i*t3 via fma(swap(t3), CJ, t1)
// CJN<DIR> = pack(+DIR, -DIR)
template <int DIR> __device__ __forceinline__ u64 cjA() {
    return (DIR > 0) ? 0x3F800000BF800000ULL : 0xBF8000003F800000ULL;
}
template <int DIR> __device__ __forceinline__ u64 cjB() {
    return (DIR > 0) ? 0xBF8000003F800000ULL : 0x3F800000BF800000ULL;
}

// 16th roots of unity (compile-time foldable)
__device__ constexpr float kC16[16] = {
    1.0f,  0.92387953251128675613f,  0.70710678118654752440f,  0.38268343236508977173f,
    0.0f, -0.38268343236508977173f, -0.70710678118654752440f, -0.92387953251128675613f,
   -1.0f, -0.92387953251128675613f, -0.70710678118654752440f, -0.38268343236508977173f,
    0.0f,  0.38268343236508977173f,  0.70710678118654752440f,  0.92387953251128675613f};
__device__ constexpr float kS16[16] = {
    0.0f,  0.38268343236508977173f,  0.70710678118654752440f,  0.92387953251128675613f,
    1.0f,  0.92387953251128675613f,  0.70710678118654752440f,  0.38268343236508977173f,
    0.0f, -0.38268343236508977173f, -0.70710678118654752440f, -0.92387953251128675613f,
   -1.0f, -0.92387953251128675613f, -0.70710678118654752440f, -0.38268343236508977173f};

// a * (c, DIR*s) with c=kC16[m], s=kS16[m]; m is a literal after unroll.
template <int DIR>
__device__ __forceinline__ u64 pcw(u64 a, int m) {
    const float cc = kC16[m & 15];
    const float ss = (float)DIR * kS16[m & 15];
    u64 cross = pmul(pswap(a), pk2(-ss, ss));   // (-s*y, s*x)
    if (cc == 0.0f) return cross;               // folds at compile time
    return pfma(a, pk2(cc, cc), cross);         // (c*x - s*y, c*y + s*x)
}

template <int DIR>
__device__ __forceinline__ void fft16p(u64 v[16]) {
    u64 u[16];
#pragma unroll
    for (int q = 0; q < 4; ++q) {
        u64 a = v[q], b = v[q + 4], c = v[q + 8], d = v[q + 12];
        u64 t0 = padd(a, c), t1 = psub(a, c), t2 = padd(b, d), t3 = psub(b, d);
        u64 s3 = pswap(t3);
        u[4 * q + 0] = padd(t0, t2);
        u[4 * q + 1] = pfma(s3, cjA<DIR>(), t1);
        u[4 * q + 2] = psub(t0, t2);
        u[4 * q + 3] = pfma(s3, cjB<DIR>(), t1);
    }
#pragma unroll
    for (int q = 0; q < 4; ++q) {
        u64 a = u[q];
        u64 b = (q == 0) ? u[q + 4]  : pcw<DIR>(u[q + 4], q);
        u64 c = (q == 0) ? u[q + 8]  : pcw<DIR>(u[q + 8], 2 * q);
        u64 d = (q == 0) ? u[q + 12] : pcw<DIR>(u[q + 12], 3 * q);
        u64 t0 = padd(a, c), t1 = psub(a, c), t2 = padd(b, d), t3 = psub(b, d);
        u64 s3 = pswap(t3);
        v[q]      = padd(t0, t2);
        v[q + 4]  = pfma(s3, cjA<DIR>(), t1);
        v[q + 8]  = psub(t0, t2);
        v[q + 12] = pfma(s3, cjB<DIR>(), t1);
    }
}

__device__ __forceinline__ int pad(int i) { return i + (i >> 4); }
#define SMEM_ELEMS (L_FFT + (L_FFT >> 4))  // 4352

// twiddle: v[r] *= exp(i*r*ang), |ang| < 0.4 rad -> MUFU __sincosf safe.
// Scalar apply (half-reads of packed regs are free), scalar power recurrence.
__device__ __forceinline__ void twp(u64 v[16], float ang) {
    float sn, cs;
    __sincosf(ang, &sn, &cs);
    float wx = cs, wy = sn;   // w^1
    float cx = cs, cy = sn;   // running w^r
#pragma unroll
    for (int r = 1; r < 16; ++r) {
        float x, y; upk(v[r], x, y);
        float rx = fmaf(x, cx, -y * cy);
        float ry = fmaf(x, cy,  y * cx);
        v[r] = pk2(rx, ry);
        if (r < 15) {
            float nx = fmaf(cx, wx, -cy * wy);
            float ny = fmaf(cx, wy,  cy * wx);
            cx = nx; cy = ny;
        }
    }
}

// Full 4096-pt FFT, 256 threads. In: v[r] = in[j+256r]. Out: v[k] = out[j+256k].
template <int DIR>
__device__ __forceinline__ void fft4096p(u64 v[16], u64* s, int j) {
    const float TWO_PI = 6.28318530717958647692f;
    fft16p<DIR>(v);
#pragma unroll
    for (int k = 0; k < 16; ++k) s[pad(16 * j + k)] = v[k];
    __syncthreads();
    {
#pragma unroll
        for (int r = 0; r < 16; ++r) v[r] = s[pad(j + 256 * r)];
        twp(v, (float)DIR * (TWO_PI / 256.0f) * (float)(j & 15));
        fft16p<DIR>(v);
        int idxD = (j >> 4) * 256 + (j & 15);
        __syncthreads();
#pragma unroll
        for (int k = 0; k < 16; ++k) s[pad(idxD + 16 * k)] = v[k];
    }
    __syncthreads();
    {
#pragma unroll
        for (int r = 0; r < 16; ++r) v[r] = s[pad(j + 256 * r)];
        twp(v, (float)DIR * (TWO_PI / 4096.0f) * (float)j);
        fft16p<DIR>(v);
    }
}

// ---------------- Kernel 1: fused forward FFTs ----------------
__global__ __launch_bounds__(NTHREADS) void k_fft_rx(const float* __restrict__ x,
                                                     const float* __restrict__ wp,
                                                     const float* __restrict__ fp) {
    __shared__ u64 s[SMEM_ELEMS];
    __shared__ float red[8];
    int j = threadIdx.x;

    if (blockIdx.x < BP) {
        int bp = blockIdx.x;
        const float* x1 = x + (size_t)(2 * bp) * L_FFT;
        const float* x2 = x + (size_t)(2 * bp + 1) * L_FFT;
        u64 v[16];
#pragma unroll
        for (int r = 0; r < 16; ++r) {
            int i = j + 256 * r;
            v[r] = pk2(x1[i], x2[i]);
        }
        fft4096p<-1>(v, s, j);
        u64* Z = (u64*)g_Zf + (size_t)bp * L_FFT;
#pragma unroll
        for (int k = 0; k < 16; ++k) Z[j + 256 * k] = v[k];
    } else {
        int f = blockIdx.x - BP;
        const float* row = wp + (size_t)f * L_FFT;

        float w[16];
        float mx = -3.4e38f;
#pragma unroll
        for (int r = 0; r < 16; ++r) {
            w[r] = row[j + 256 * r];
            mx = fmaxf(mx, w[r]);
        }
#pragma unroll
        for (int off = 16; off; off >>= 1) mx = fmaxf(mx, __shfl_xor_sync(0xffffffffu, mx, off));
        if ((j & 31) == 0) red[j >> 5] = mx;
        __syncthreads();
        float bm = red[0];
#pragma unroll
        for (int i = 1; i < 8; ++i) bm = fmaxf(bm, red[i]);
        __syncthreads();

        float se = 0.0f;
#pragma unroll
        for (int r = 0; r < 16; ++r) {
            w[r] = __expf(w[r] - bm);  // fast exp: softmax tolerance-safe
            se += w[r];
        }
#pragma unroll
        for (int off = 16; off; off >>= 1) se += __shfl_xor_sync(0xffffffffu, se, off);
        if ((j & 31) == 0) red[j >> 5] = se;
        __syncthreads();
        float bs = 0.0f;
#pragma unroll
        for (int i = 0; i < 8; ++i) bs += red[i];
        __syncthreads();

        float scale = 1.0f / (bs * (float)L_FFT);  // softmax norm + ifft 1/L
        float freq = 0.5f / (1.0f + __expf(-fp[f]));
        float a = -6.2831853071795864769f * freq;

        // cos(a*(j+256r)) via one precise sincos + 15-step rotation by 256a.
        float c0, s0, rc, rs;
        sincosf(a * (float)j, &s0, &c0);
        sincosf(a * 256.0f, &rs, &rc);

        u64 v[16];
        float cx = c0, sx = s0;
#pragma unroll
        for (int r = 0; r < 16; ++r) {
            v[r] = pk2(w[r] * scale * cx, 0.0f);
            float nc = fmaf(cx, rc, -sx * rs);
            float ns = fmaf(cx, rs,  sx * rc);
            cx = nc; sx = ns;
        }
        fft4096p<-1>(v, s, j);
        u64* R = (u64*)g_Rf + (size_t)f * L_FFT;
#pragma unroll
        for (int k = 0; k < 16; ++k) R[j + 256 * k] = v[k];
    }
}

// ---------------- Kernel 2: product + inverse FFT + write ----------------
__global__ __launch_bounds__(NTHREADS) void k_main(float* __restrict__ out) {
    __shared__ u64 s[SMEM_ELEMS];
    int f = blockIdx.x;
    int bp = blockIdx.y;
    int j = threadIdx.x;

    const float2* __restrict__ Z = g_Zf + (size_t)bp * L_FFT;
    const float2* __restrict__ R = g_Rf + (size_t)f * L_FFT;

    u64 v[16];
#pragma unroll
    for (int r = 0; r < 16; ++r) {
        int i = j + 256 * r;
        float2 z = Z[i];
        float2 rr = R[i];
        // z * conj(r); 1/L folded into R
        float px = fmaf(z.x, rr.x, z.y * rr.y);
        float py = fmaf(z.y, rr.x, -z.x * rr.y);
        v[r] = pk2(px, py);
    }
    fft4096p<1>(v, s, j);  // inverse, unscaled

    float* __restrict__ o1 = out + ((size_t)(2 * bp) * F_FILT + f) * L_FFT;
    float* __restrict__ o2 = out + ((size_t)(2 * bp + 1) * F_FILT + f) * L_FFT;
#pragma unroll
    for (int k = 0; k < 16; ++k) {
        int i = j + 256 * k;
        float a, b; upk(v[k], a, b);
        __stcs(o1 + i, a);  // streaming stores: keep Z/R resident in L2
        __stcs(o2 + i, b);
    }
}

extern "C" void kernel_launch(void* const* d_in, const int* in_sizes, int n_in,
                              void* d_out, int out_size) {
    (void)in_sizes; (void)n_in; (void)out_size;
    const float* x  = (const float*)d_in[0];
    const float* wp = (const float*)d_in[1];
    const float* fp = (const float*)d_in[2];
    float* out = (float*)d_out;

    k_fft_rx<<<BP + F_FILT, NTHREADS>>>(x, wp, fp);
    dim3 grid(F_FILT, BP);
    k_main<<<grid, NTHREADS>>>(out);
}